// round 2
// baseline (speedup 1.0000x reference)
#include <cuda_runtime.h>
#include <cstdint>

#define N_INP 128
#define N_HID 512
#define N_OUT 256
#define N_HEADS 64
#define N_SM 4
#define EPS_GN 1e-5f
#define TINY 1e-14f

// scratch (device globals; allocation-free)
__device__ float g_h1[N_HEADS * N_HID];          // 64*512
__device__ float g_zsm[N_SM * N_HEADS * N_OUT];  // 4*64*256 softmax results
__device__ float g_scalar[N_HEADS * N_OUT];      // ws row sums

__device__ __forceinline__ float warp_sum(float v) {
#pragma unroll
    for (int o = 16; o > 0; o >>= 1) v += __shfl_xor_sync(0xffffffffu, v, o);
    return v;
}
__device__ __forceinline__ float warp_max(float v) {
#pragma unroll
    for (int o = 16; o > 0; o >>= 1) v = fmaxf(v, __shfl_xor_sync(0xffffffffu, v, o));
    return v;
}

// block reduce sum, broadcast to all threads. red must hold >= 32 floats.
__device__ __forceinline__ float block_sum(float v, float* red) {
    int lane = threadIdx.x & 31, warp = threadIdx.x >> 5;
    int nw = blockDim.x >> 5;
    v = warp_sum(v);
    if (lane == 0) red[warp] = v;
    __syncthreads();
    float r = (threadIdx.x < nw) ? red[threadIdx.x] : 0.f;
    if (warp == 0) {
        r = warp_sum(r);
        if (lane == 0) red[0] = r;
    }
    __syncthreads();
    float out = red[0];
    __syncthreads();
    return out;
}
__device__ __forceinline__ float block_max(float v, float* red) {
    int lane = threadIdx.x & 31, warp = threadIdx.x >> 5;
    int nw = blockDim.x >> 5;
    v = warp_max(v);
    if (lane == 0) red[warp] = v;
    __syncthreads();
    float r = (threadIdx.x < nw) ? red[threadIdx.x] : -3.4e38f;
    if (warp == 0) {
        r = warp_max(r);
        if (lane == 0) red[0] = r;
    }
    __syncthreads();
    float out = red[0];
    __syncthreads();
    return out;
}

// ---------------------------------------------------------------------------
// Kernel 1: per head h — sub = x @ qw_h ; h1 = softplus(GN(w1_h @ sub))
// grid: 64 blocks, 512 threads
// ---------------------------------------------------------------------------
__global__ __launch_bounds__(512) void k1_sub_h1(
    const float* __restrict__ x, const float* __restrict__ qw,
    const float* __restrict__ w1, const float* __restrict__ g1g,
    const float* __restrict__ g1b)
{
    int h = blockIdx.x;
    __shared__ float qws[N_INP];
    __shared__ float subs[N_INP];
    __shared__ float y[N_HID];
    __shared__ float red[32];

    int tid = threadIdx.x;
    int warp = tid >> 5, lane = tid & 31;

    if (tid < N_INP) qws[tid] = qw[h * N_INP + tid];
    __syncthreads();

    // sub[r] = dot(x[r,:], qw_h)  — 128 rows, 16 warps
    float q0 = qws[lane * 4 + 0], q1 = qws[lane * 4 + 1],
          q2 = qws[lane * 4 + 2], q3 = qws[lane * 4 + 3];
    for (int r = warp; r < N_INP; r += 16) {
        float4 xv = *(const float4*)(x + r * N_INP + lane * 4);
        float s = xv.x * q0 + xv.y * q1 + xv.z * q2 + xv.w * q3;
        s = warp_sum(s);
        if (lane == 0) subs[r] = s;
    }
    __syncthreads();

    float s0 = subs[lane * 4 + 0], s1 = subs[lane * 4 + 1],
          s2 = subs[lane * 4 + 2], s3 = subs[lane * 4 + 3];
    const float* w1h = w1 + (size_t)h * N_HID * N_INP;
    for (int o = warp; o < N_HID; o += 16) {
        float4 wv = *(const float4*)(w1h + (size_t)o * N_INP + lane * 4);
        float acc = wv.x * s0 + wv.y * s1 + wv.z * s2 + wv.w * s3;
        acc = warp_sum(acc);
        if (lane == 0) y[o] = acc;
    }
    __syncthreads();

    float v = y[tid];
    float sum = block_sum(v, red);
    float sq  = block_sum(v * v, red);
    float mu = sum * (1.f / N_HID);
    float var = sq * (1.f / N_HID) - mu * mu;
    float rstd = rsqrtf(var + EPS_GN);

    float t = (v - mu) * rstd * g1g[h * N_HID + tid] + g1b[h * N_HID + tid];
    // stable softplus = max(t,0) + log1p(exp(-|t|))
    float sp = fmaxf(t, 0.f) + log1pf(expf(-fabsf(t)));
    g_h1[h * N_HID + tid] = sp;
}

// ---------------------------------------------------------------------------
// Kernel 2: per (s,h) block — z = GN(w2[s,h] @ h1[h]) ; softmax -> g_zsm
// grid: 256 blocks, 512 threads. Carries 128 MB of w2 (the roofline).
// ---------------------------------------------------------------------------
__global__ __launch_bounds__(512) void k2_z_softmax(
    const float* __restrict__ w2, const float* __restrict__ g2g,
    const float* __restrict__ g2b)
{
    int bid = blockIdx.x;            // bid = s*64 + h
    int h = bid & 63;
    __shared__ float h1s[N_HID];
    __shared__ float z[N_OUT];
    __shared__ float red[32];

    int tid = threadIdx.x;
    int warp = tid >> 5, lane = tid & 31;

    h1s[tid] = g_h1[h * N_HID + tid];
    __syncthreads();

    float hv[4];
#pragma unroll
    for (int k = 0; k < 4; k++) hv[k] = 0.f; // silence
    // cache the 16 h1 values this lane uses
    float ha[4][4];
#pragma unroll
    for (int k = 0; k < 4; k++) {
        ha[k][0] = h1s[k * 128 + lane * 4 + 0];
        ha[k][1] = h1s[k * 128 + lane * 4 + 1];
        ha[k][2] = h1s[k * 128 + lane * 4 + 2];
        ha[k][3] = h1s[k * 128 + lane * 4 + 3];
    }
    (void)hv;

    const float* wp = w2 + (size_t)bid * N_OUT * N_HID;
    for (int o = warp; o < N_OUT; o += 16) {
        const float* row = wp + (size_t)o * N_HID + lane * 4;
        float acc = 0.f;
#pragma unroll
        for (int k = 0; k < 4; k++) {
            float4 wv = *(const float4*)(row + k * 128);
            acc += wv.x * ha[k][0] + wv.y * ha[k][1] + wv.z * ha[k][2] + wv.w * ha[k][3];
        }
        acc = warp_sum(acc);
        if (lane == 0) z[o] = acc;
    }
    __syncthreads();

    float v = (tid < N_OUT) ? z[tid] : 0.f;
    float sum = block_sum(v, red);
    float sq  = block_sum(v * v, red);
    float mu = sum * (1.f / N_OUT);
    float var = sq * (1.f / N_OUT) - mu * mu;
    float rstd = rsqrtf(var + EPS_GN);

    float zn = (tid < N_OUT)
                   ? (v - mu) * rstd * g2g[bid * N_OUT + tid] + g2b[bid * N_OUT + tid]
                   : -3.4e38f;
    float zmax = block_max(zn, red);
    float e = (tid < N_OUT) ? expf(zn - zmax) : 0.f;
    float denom = block_sum(e, red);
    if (tid < N_OUT) g_zsm[bid * N_OUT + tid] = e / denom;
}

// ---------------------------------------------------------------------------
// Kernel 3: scalar[h,o] = sum_i ws[h,o,i]  (16384 rows of 256)
// warp per row; 8 warps per block -> 2048 blocks
// ---------------------------------------------------------------------------
__global__ __launch_bounds__(256) void k3_ws_sum(const float* __restrict__ ws)
{
    int warp = threadIdx.x >> 5, lane = threadIdx.x & 31;
    int row = blockIdx.x * 8 + warp;   // row = h*256 + o
    const float* p = ws + (size_t)row * N_OUT + lane * 4;
    float4 a = *(const float4*)(p);
    float4 b = *(const float4*)(p + 128);
    float s = a.x + a.y + a.z + a.w + b.x + b.y + b.z + b.w;
    s = warp_sum(s);
    if (lane == 0) g_scalar[row] = s;
}

// ---------------------------------------------------------------------------
// Kernel 4: epilogue per head — gate + outputs
// grid: 64 blocks, 256 threads
// out layout: [0:16384) = clip(on_off*out_sm, TINY), [16384:32768) = out_scaled
// ---------------------------------------------------------------------------
__global__ __launch_bounds__(256) void k4_final(
    const float* __restrict__ last, const float* __restrict__ woo,
    float* __restrict__ out)
{
    int h = blockIdx.x;
    int o = threadIdx.x;
    __shared__ float red[32];

    // last_prod[o] = prod_j last[o, j]
    float lp = 1.f;
    const float* lr = last + o * N_HEADS;
#pragma unroll
    for (int j = 0; j < N_HEADS; j++) lp *= lr[j];

    // out_sm[o,h] = sum_s zsm[s,h,o]
    float osm = 0.f;
#pragma unroll
    for (int s = 0; s < N_SM; s++) osm += g_zsm[((s * N_HEADS + h) << 8) + o];

    float part = woo[h * 512 + o] * lp + woo[h * 512 + N_OUT + o] * osm;
    float logit = block_sum(part, red);
    float on_off = 1.f / (1.f + expf(-logit));

    float v = on_off * osm;
    out[o * N_HEADS + h] = fmaxf(v, TINY);
    float sc = v * g_scalar[h * N_OUT + o];
    out[N_OUT * N_HEADS + o * N_HEADS + h] = (fabsf(sc) <= TINY) ? TINY : sc;
}

extern "C" void kernel_launch(void* const* d_in, const int* in_sizes, int n_in,
                              void* d_out, int out_size)
{
    const float* x    = (const float*)d_in[0];
    const float* last = (const float*)d_in[1];
    const float* qw   = (const float*)d_in[2];
    const float* w1   = (const float*)d_in[3];
    const float* g1g  = (const float*)d_in[4];
    const float* g1b  = (const float*)d_in[5];
    const float* w2   = (const float*)d_in[6];
    const float* g2g  = (const float*)d_in[7];
    const float* g2b  = (const float*)d_in[8];
    const float* ws   = (const float*)d_in[9];
    const float* woo  = (const float*)d_in[10];
    float* out = (float*)d_out;

    k1_sub_h1<<<N_HEADS, 512>>>(x, qw, w1, g1g, g1b);
    k2_z_softmax<<<N_SM * N_HEADS, 512>>>(w2, g2g, g2b);
    k3_ws_sum<<<(N_HEADS * N_OUT) / 8, 256>>>(ws);
    k4_final<<<N_HEADS, 256>>>(last, woo, out);
}

// round 3
// speedup vs baseline: 1.1938x; 1.1938x over previous
#include <cuda_runtime.h>
#include <cstdint>

#define N_INP 128
#define N_HID 512
#define N_OUT 256
#define N_HEADS 64
#define N_SM 4
#define EPS_GN 1e-5f
#define TINY 1e-14f

// scratch (device globals; allocation-free)
__device__ float g_h1[N_HEADS * N_HID];          // 64*512
__device__ float g_z[N_SM * N_HEADS * N_OUT];    // raw z before GN/softmax
__device__ float g_scalar[N_HEADS * N_OUT];      // ws row sums
__device__ float g_lp[N_OUT];                    // last_prod

__device__ __forceinline__ float warp_sum(float v) {
#pragma unroll
    for (int o = 16; o > 0; o >>= 1) v += __shfl_xor_sync(0xffffffffu, v, o);
    return v;
}
__device__ __forceinline__ float warp_prod(float v) {
#pragma unroll
    for (int o = 16; o > 0; o >>= 1) v *= __shfl_xor_sync(0xffffffffu, v, o);
    return v;
}
__device__ __forceinline__ float4 warp_sum4(float4 v) {
#pragma unroll
    for (int o = 16; o > 0; o >>= 1) {
        v.x += __shfl_xor_sync(0xffffffffu, v.x, o);
        v.y += __shfl_xor_sync(0xffffffffu, v.y, o);
        v.z += __shfl_xor_sync(0xffffffffu, v.z, o);
        v.w += __shfl_xor_sync(0xffffffffu, v.w, o);
    }
    return v;
}
__device__ __forceinline__ float4 warp_max4(float4 v) {
#pragma unroll
    for (int o = 16; o > 0; o >>= 1) {
        v.x = fmaxf(v.x, __shfl_xor_sync(0xffffffffu, v.x, o));
        v.y = fmaxf(v.y, __shfl_xor_sync(0xffffffffu, v.y, o));
        v.z = fmaxf(v.z, __shfl_xor_sync(0xffffffffu, v.z, o));
        v.w = fmaxf(v.w, __shfl_xor_sync(0xffffffffu, v.w, o));
    }
    return v;
}

// block reduce sum (scalar), broadcast. red >= 32 floats.
__device__ __forceinline__ float block_sum(float v, float* red) {
    int lane = threadIdx.x & 31, warp = threadIdx.x >> 5;
    int nw = blockDim.x >> 5;
    v = warp_sum(v);
    if (lane == 0) red[warp] = v;
    __syncthreads();
    float r = (threadIdx.x < nw) ? red[threadIdx.x] : 0.f;
    if (warp == 0) {
        r = warp_sum(r);
        if (lane == 0) red[0] = r;
    }
    __syncthreads();
    float out = red[0];
    __syncthreads();
    return out;
}

// block reduce float4 (sum), broadcast. red4 >= 32 float4.
__device__ __forceinline__ float4 block_sum4(float4 v, float4* red4) {
    int lane = threadIdx.x & 31, warp = threadIdx.x >> 5;
    int nw = blockDim.x >> 5;
    v = warp_sum4(v);
    if (lane == 0) red4[warp] = v;
    __syncthreads();
    float4 r = (threadIdx.x < nw) ? red4[threadIdx.x] : make_float4(0.f, 0.f, 0.f, 0.f);
    if (warp == 0) {
        r = warp_sum4(r);
        if (lane == 0) red4[0] = r;
    }
    __syncthreads();
    float4 out = red4[0];
    __syncthreads();
    return out;
}
__device__ __forceinline__ float4 block_max4(float4 v, float4* red4) {
    int lane = threadIdx.x & 31, warp = threadIdx.x >> 5;
    int nw = blockDim.x >> 5;
    const float NEG = -3.4e38f;
    v = warp_max4(v);
    if (lane == 0) red4[warp] = v;
    __syncthreads();
    float4 r = (threadIdx.x < nw) ? red4[threadIdx.x] : make_float4(NEG, NEG, NEG, NEG);
    if (warp == 0) {
        r = warp_max4(r);
        if (lane == 0) red4[0] = r;
    }
    __syncthreads();
    float4 out = red4[0];
    __syncthreads();
    return out;
}

// ---------------------------------------------------------------------------
// Kernel A (fused): bid<64: per-head k1 (sub, h1)
//                   64<=bid<1088: ws row sums (16 rows/block)
//                   1088<=bid<1104: last_prod (16 o's/block, coalesced)
// 1104 blocks x 512 threads
// ---------------------------------------------------------------------------
__global__ __launch_bounds__(512) void kA(
    const float* __restrict__ x, const float* __restrict__ qw,
    const float* __restrict__ w1, const float* __restrict__ g1g,
    const float* __restrict__ g1b, const float* __restrict__ ws,
    const float* __restrict__ last)
{
    int bid = blockIdx.x;
    int tid = threadIdx.x;
    int warp = tid >> 5, lane = tid & 31;

    if (bid >= 1088) {
        // last_prod: warp handles o; lanes cover 64 j's (2 each), warp product
        int o = (bid - 1088) * 16 + warp;
        float v = last[o * N_HEADS + lane] * last[o * N_HEADS + 32 + lane];
        v = warp_prod(v);
        if (lane == 0) g_lp[o] = v;
        return;
    }
    if (bid >= 64) {
        // ws row sums: row = h*256+o
        int row = (bid - 64) * 16 + warp;
        const float* p = ws + (size_t)row * N_OUT + lane * 4;
        float4 a = *(const float4*)(p);
        float4 b = *(const float4*)(p + 128);
        float s = a.x + a.y + a.z + a.w + b.x + b.y + b.z + b.w;
        s = warp_sum(s);
        if (lane == 0) g_scalar[row] = s;
        return;
    }

    // --- k1: per head ---
    int h = bid;
    __shared__ float qws[N_INP];
    __shared__ float subs[N_INP];
    __shared__ float y[N_HID];
    __shared__ float red[32];

    if (tid < N_INP) qws[tid] = qw[h * N_INP + tid];
    __syncthreads();

    float q0 = qws[lane * 4 + 0], q1 = qws[lane * 4 + 1],
          q2 = qws[lane * 4 + 2], q3 = qws[lane * 4 + 3];
    for (int r = warp; r < N_INP; r += 16) {
        float4 xv = *(const float4*)(x + r * N_INP + lane * 4);
        float s = xv.x * q0 + xv.y * q1 + xv.z * q2 + xv.w * q3;
        s = warp_sum(s);
        if (lane == 0) subs[r] = s;
    }
    __syncthreads();

    float s0 = subs[lane * 4 + 0], s1 = subs[lane * 4 + 1],
          s2 = subs[lane * 4 + 2], s3 = subs[lane * 4 + 3];
    const float* w1h = w1 + (size_t)h * N_HID * N_INP;
    for (int o = warp; o < N_HID; o += 16) {
        float4 wv = *(const float4*)(w1h + (size_t)o * N_INP + lane * 4);
        float acc = wv.x * s0 + wv.y * s1 + wv.z * s2 + wv.w * s3;
        acc = warp_sum(acc);
        if (lane == 0) y[o] = acc;
    }
    __syncthreads();

    float v = y[tid];
    float sum = block_sum(v, red);
    float sq  = block_sum(v * v, red);
    float mu = sum * (1.f / N_HID);
    float var = sq * (1.f / N_HID) - mu * mu;
    float rstd = rsqrtf(var + EPS_GN);

    float t = (v - mu) * rstd * g1g[h * N_HID + tid] + g1b[h * N_HID + tid];
    float sp = fmaxf(t, 0.f) + log1pf(expf(-fabsf(t)));
    g_h1[h * N_HID + tid] = sp;
}

// ---------------------------------------------------------------------------
// Kernel B: raw z = w2[s,h] @ h1[h], split 4 ways over output rows.
// grid: 1024 blocks (bid = sh*4 + quarter), 512 threads. Carries the 128 MB.
// ---------------------------------------------------------------------------
__global__ __launch_bounds__(512) void kB(const float* __restrict__ w2)
{
    int bid = blockIdx.x;
    int sh = bid >> 2;          // s*64 + h
    int q  = bid & 3;
    int h = sh & 63;
    __shared__ float h1s[N_HID];

    int tid = threadIdx.x;
    int warp = tid >> 5, lane = tid & 31;

    h1s[tid] = g_h1[h * N_HID + tid];
    __syncthreads();

    float ha[4][4];
#pragma unroll
    for (int k = 0; k < 4; k++) {
        ha[k][0] = h1s[k * 128 + lane * 4 + 0];
        ha[k][1] = h1s[k * 128 + lane * 4 + 1];
        ha[k][2] = h1s[k * 128 + lane * 4 + 2];
        ha[k][3] = h1s[k * 128 + lane * 4 + 3];
    }

    const float* wp = w2 + (size_t)sh * N_OUT * N_HID;
    // this block handles rows [q*64, q*64+64); warp does 4 rows (stride 16)
#pragma unroll
    for (int r = 0; r < 4; r++) {
        int o = q * 64 + r * 16 + warp;
        const float* row = wp + (size_t)o * N_HID + lane * 4;
        float acc = 0.f;
#pragma unroll
        for (int k = 0; k < 4; k++) {
            float4 wv = *(const float4*)(row + k * 128);
            acc += wv.x * ha[k][0] + wv.y * ha[k][1] + wv.z * ha[k][2] + wv.w * ha[k][3];
        }
        acc = warp_sum(acc);
        if (lane == 0) g_z[sh * N_OUT + o] = acc;
    }
}

// ---------------------------------------------------------------------------
// Kernel C: per-head epilogue. 64 blocks x 256 threads (thread = o).
// GN+softmax for all 4 s (batched float4 reductions), sum over s, gate,
// outputs.
// ---------------------------------------------------------------------------
__global__ __launch_bounds__(256) void kC(
    const float* __restrict__ g2g, const float* __restrict__ g2b,
    const float* __restrict__ woo, float* __restrict__ out)
{
    int h = blockIdx.x;
    int o = threadIdx.x;
    __shared__ float4 red4[32];
    __shared__ float red[32];

    float z[N_SM];
#pragma unroll
    for (int s = 0; s < N_SM; s++) z[s] = g_z[((s * N_HEADS + h) << 8) + o];

    float4 zsum = block_sum4(make_float4(z[0], z[1], z[2], z[3]), red4);
    float4 zsq  = block_sum4(make_float4(z[0]*z[0], z[1]*z[1], z[2]*z[2], z[3]*z[3]), red4);

    float zn[N_SM];
    {
        float mus[4] = {zsum.x, zsum.y, zsum.z, zsum.w};
        float sqs[4] = {zsq.x, zsq.y, zsq.z, zsq.w};
#pragma unroll
        for (int s = 0; s < N_SM; s++) {
            float mu = mus[s] * (1.f / N_OUT);
            float var = sqs[s] * (1.f / N_OUT) - mu * mu;
            float rstd = rsqrtf(var + EPS_GN);
            int idx = ((s * N_HEADS + h) << 8) + o;
            zn[s] = (z[s] - mu) * rstd * g2g[idx] + g2b[idx];
        }
    }

    float4 zmax = block_max4(make_float4(zn[0], zn[1], zn[2], zn[3]), red4);
    float e[N_SM];
    e[0] = expf(zn[0] - zmax.x);
    e[1] = expf(zn[1] - zmax.y);
    e[2] = expf(zn[2] - zmax.z);
    e[3] = expf(zn[3] - zmax.w);
    float4 denom = block_sum4(make_float4(e[0], e[1], e[2], e[3]), red4);

    float osm = e[0] / denom.x + e[1] / denom.y + e[2] / denom.z + e[3] / denom.w;

    float lp = g_lp[o];
    float part = woo[h * 512 + o] * lp + woo[h * 512 + N_OUT + o] * osm;
    float logit = block_sum(part, red);
    float on_off = 1.f / (1.f + expf(-logit));

    float v = on_off * osm;
    out[o * N_HEADS + h] = fmaxf(v, TINY);
    float sc = v * g_scalar[h * N_OUT + o];
    out[N_OUT * N_HEADS + o * N_HEADS + h] = (fabsf(sc) <= TINY) ? TINY : sc;
}

extern "C" void kernel_launch(void* const* d_in, const int* in_sizes, int n_in,
                              void* d_out, int out_size)
{
    const float* x    = (const float*)d_in[0];
    const float* last = (const float*)d_in[1];
    const float* qw   = (const float*)d_in[2];
    const float* w1   = (const float*)d_in[3];
    const float* g1g  = (const float*)d_in[4];
    const float* g1b  = (const float*)d_in[5];
    const float* w2   = (const float*)d_in[6];
    const float* g2g  = (const float*)d_in[7];
    const float* g2b  = (const float*)d_in[8];
    const float* ws   = (const float*)d_in[9];
    const float* woo  = (const float*)d_in[10];
    float* out = (float*)d_out;

    kA<<<1104, 512>>>(x, qw, w1, g1g, g1b, ws, last);
    kB<<<1024, 512>>>(w2);
    kC<<<N_HEADS, 256>>>(g2g, g2b, woo, out);
}

// round 4
// speedup vs baseline: 1.4363x; 1.2031x over previous
#include <cuda_runtime.h>
#include <cstdint>

#define N_INP 128
#define N_HID 512
#define N_OUT 256
#define N_HEADS 64
#define N_SM 4
#define EPS_GN 1e-5f
#define TINY 1e-14f

// scratch (device globals; allocation-free)
__device__ float g_y[N_HEADS * N_HID];           // pre-GN l1 output
__device__ float g_h1[N_HEADS * N_HID];          // post GN+softplus
__device__ float g_z[N_SM * N_HEADS * N_OUT];    // raw z before GN/softmax
__device__ float g_scalar[N_HEADS * N_OUT];      // ws row sums
__device__ float g_lp[N_OUT];                    // last_prod

__device__ __forceinline__ float warp_sum(float v) {
#pragma unroll
    for (int o = 16; o > 0; o >>= 1) v += __shfl_xor_sync(0xffffffffu, v, o);
    return v;
}
__device__ __forceinline__ float warp_prod(float v) {
#pragma unroll
    for (int o = 16; o > 0; o >>= 1) v *= __shfl_xor_sync(0xffffffffu, v, o);
    return v;
}
__device__ __forceinline__ float4 warp_sum4(float4 v) {
#pragma unroll
    for (int o = 16; o > 0; o >>= 1) {
        v.x += __shfl_xor_sync(0xffffffffu, v.x, o);
        v.y += __shfl_xor_sync(0xffffffffu, v.y, o);
        v.z += __shfl_xor_sync(0xffffffffu, v.z, o);
        v.w += __shfl_xor_sync(0xffffffffu, v.w, o);
    }
    return v;
}
__device__ __forceinline__ float4 warp_max4(float4 v) {
#pragma unroll
    for (int o = 16; o > 0; o >>= 1) {
        v.x = fmaxf(v.x, __shfl_xor_sync(0xffffffffu, v.x, o));
        v.y = fmaxf(v.y, __shfl_xor_sync(0xffffffffu, v.y, o));
        v.z = fmaxf(v.z, __shfl_xor_sync(0xffffffffu, v.z, o));
        v.w = fmaxf(v.w, __shfl_xor_sync(0xffffffffu, v.w, o));
    }
    return v;
}

__device__ __forceinline__ float block_sum(float v, float* red) {
    int lane = threadIdx.x & 31, warp = threadIdx.x >> 5;
    int nw = blockDim.x >> 5;
    v = warp_sum(v);
    if (lane == 0) red[warp] = v;
    __syncthreads();
    float r = (threadIdx.x < nw) ? red[threadIdx.x] : 0.f;
    if (warp == 0) {
        r = warp_sum(r);
        if (lane == 0) red[0] = r;
    }
    __syncthreads();
    float out = red[0];
    __syncthreads();
    return out;
}
__device__ __forceinline__ float4 block_sum4(float4 v, float4* red4) {
    int lane = threadIdx.x & 31, warp = threadIdx.x >> 5;
    int nw = blockDim.x >> 5;
    v = warp_sum4(v);
    if (lane == 0) red4[warp] = v;
    __syncthreads();
    float4 r = (threadIdx.x < nw) ? red4[threadIdx.x] : make_float4(0.f, 0.f, 0.f, 0.f);
    if (warp == 0) {
        r = warp_sum4(r);
        if (lane == 0) red4[0] = r;
    }
    __syncthreads();
    float4 out = red4[0];
    __syncthreads();
    return out;
}
__device__ __forceinline__ float4 block_max4(float4 v, float4* red4) {
    int lane = threadIdx.x & 31, warp = threadIdx.x >> 5;
    int nw = blockDim.x >> 5;
    const float NEG = -3.4e38f;
    v = warp_max4(v);
    if (lane == 0) red4[warp] = v;
    __syncthreads();
    float4 r = (threadIdx.x < nw) ? red4[threadIdx.x] : make_float4(NEG, NEG, NEG, NEG);
    if (warp == 0) {
        r = warp_max4(r);
        if (lane == 0) red4[0] = r;
    }
    __syncthreads();
    float4 out = red4[0];
    __syncthreads();
    return out;
}

// ---------------------------------------------------------------------------
// K1: 256 blocks (h,quarter) x 512. Recompute sub_h from L2-resident x, then
// 128 rows of w1 -> g_y. 4-row batched float4 reductions.
// ---------------------------------------------------------------------------
__global__ __launch_bounds__(512) void K1(
    const float* __restrict__ x, const float* __restrict__ qw,
    const float* __restrict__ w1)
{
    int h = blockIdx.x >> 2;
    int q = blockIdx.x & 3;
    int tid = threadIdx.x;
    int warp = tid >> 5, lane = tid & 31;

    __shared__ float qws[N_INP];
    __shared__ float subs[N_INP];

    if (tid < N_INP) qws[tid] = qw[h * N_INP + tid];
    __syncthreads();

    float q0 = qws[lane * 4 + 0], q1 = qws[lane * 4 + 1],
          q2 = qws[lane * 4 + 2], q3 = qws[lane * 4 + 3];

    // sub: 128 rows, 16 warps, 8 rows/warp in 2 groups of 4
#pragma unroll
    for (int g = 0; g < 2; g++) {
        int r0 = warp * 8 + g * 4;
        float p[4];
#pragma unroll
        for (int i = 0; i < 4; i++) {
            float4 xv = *(const float4*)(x + (r0 + i) * N_INP + lane * 4);
            p[i] = xv.x * q0 + xv.y * q1 + xv.z * q2 + xv.w * q3;
        }
        float4 s = warp_sum4(make_float4(p[0], p[1], p[2], p[3]));
        if (lane == 0) *(float4*)(subs + r0) = s;
    }
    __syncthreads();

    float s0 = subs[lane * 4 + 0], s1 = subs[lane * 4 + 1],
          s2 = subs[lane * 4 + 2], s3 = subs[lane * 4 + 3];

    const float* w1h = w1 + (size_t)h * N_HID * N_INP;
    // rows [q*128, q*128+128): 8 rows/warp in 2 groups of 4
#pragma unroll
    for (int g = 0; g < 2; g++) {
        int r0 = q * 128 + warp * 8 + g * 4;
        float p[4];
#pragma unroll
        for (int i = 0; i < 4; i++) {
            float4 wv = *(const float4*)(w1h + (size_t)(r0 + i) * N_INP + lane * 4);
            p[i] = wv.x * s0 + wv.y * s1 + wv.z * s2 + wv.w * s3;
        }
        float4 acc = warp_sum4(make_float4(p[0], p[1], p[2], p[3]));
        if (lane == 0) *(float4*)(g_y + h * N_HID + r0) = acc;
    }
}

// ---------------------------------------------------------------------------
// K2: GN + softplus. 64 blocks x 512.
// ---------------------------------------------------------------------------
__global__ __launch_bounds__(512) void K2(
    const float* __restrict__ g1g, const float* __restrict__ g1b)
{
    int h = blockIdx.x;
    int tid = threadIdx.x;
    __shared__ float red[32];

    float v = g_y[h * N_HID + tid];
    float sum = block_sum(v, red);
    float sq  = block_sum(v * v, red);
    float mu = sum * (1.f / N_HID);
    float var = sq * (1.f / N_HID) - mu * mu;
    float rstd = rsqrtf(var + EPS_GN);

    float t = (v - mu) * rstd * g1g[h * N_HID + tid] + g1b[h * N_HID + tid];
    float sp = fmaxf(t, 0.f) + log1pf(expf(-fabsf(t)));
    g_h1[h * N_HID + tid] = sp;
}

// ---------------------------------------------------------------------------
// K3: bid<1024: w2 matmul (per (s,h) quarter). 1024<=bid<1280: ws row sums.
//     1280<=bid<1296: last_prod. 1296 blocks x 512.
// ---------------------------------------------------------------------------
__global__ __launch_bounds__(512) void K3(
    const float* __restrict__ w2, const float* __restrict__ ws,
    const float* __restrict__ last)
{
    int bid = blockIdx.x;
    int tid = threadIdx.x;
    int warp = tid >> 5, lane = tid & 31;

    if (bid >= 1280) {
        int o = (bid - 1280) * 16 + warp;
        float v = last[o * N_HEADS + lane] * last[o * N_HEADS + 32 + lane];
        v = warp_prod(v);
        if (lane == 0) g_lp[o] = v;
        return;
    }
    if (bid >= 1024) {
        // ws: 64 rows per block, 4 rows per warp
        int r0 = (bid - 1024) * 64 + warp * 4;
        float p[4];
#pragma unroll
        for (int i = 0; i < 4; i++) {
            const float* pr = ws + (size_t)(r0 + i) * N_OUT + lane * 4;
            float4 a = *(const float4*)(pr);
            float4 b = *(const float4*)(pr + 128);
            p[i] = a.x + a.y + a.z + a.w + b.x + b.y + b.z + b.w;
        }
        float4 s = warp_sum4(make_float4(p[0], p[1], p[2], p[3]));
        if (lane == 0) *(float4*)(g_scalar + r0) = s;
        return;
    }

    // w2: bid = sh*4 + quarter
    int sh = bid >> 2;
    int q  = bid & 3;
    int h  = sh & 63;
    __shared__ float h1s[N_HID];
    h1s[tid] = g_h1[h * N_HID + tid];
    __syncthreads();

    float ha[4][4];
#pragma unroll
    for (int k = 0; k < 4; k++) {
        ha[k][0] = h1s[k * 128 + lane * 4 + 0];
        ha[k][1] = h1s[k * 128 + lane * 4 + 1];
        ha[k][2] = h1s[k * 128 + lane * 4 + 2];
        ha[k][3] = h1s[k * 128 + lane * 4 + 3];
    }

    const float* wp = w2 + (size_t)sh * N_OUT * N_HID;
    // this block: 64 rows [q*64, q*64+64); warp does 4 consecutive rows
    int r0 = q * 64 + warp * 4;
    float p[4];
#pragma unroll
    for (int i = 0; i < 4; i++) {
        const float* row = wp + (size_t)(r0 + i) * N_HID + lane * 4;
        float acc = 0.f;
#pragma unroll
        for (int k = 0; k < 4; k++) {
            float4 wv = *(const float4*)(row + k * 128);
            acc += wv.x * ha[k][0] + wv.y * ha[k][1] + wv.z * ha[k][2] + wv.w * ha[k][3];
        }
        p[i] = acc;
    }
    float4 s = warp_sum4(make_float4(p[0], p[1], p[2], p[3]));
    if (lane == 0) *(float4*)(g_z + sh * N_OUT + r0) = s;
}

// ---------------------------------------------------------------------------
// K4: per-head epilogue. 64 blocks x 256 (thread = o).
// ---------------------------------------------------------------------------
__global__ __launch_bounds__(256) void K4(
    const float* __restrict__ g2g, const float* __restrict__ g2b,
    const float* __restrict__ woo, float* __restrict__ out)
{
    int h = blockIdx.x;
    int o = threadIdx.x;
    __shared__ float4 red4[32];
    __shared__ float red[32];

    float z[N_SM];
#pragma unroll
    for (int s = 0; s < N_SM; s++) z[s] = g_z[((s * N_HEADS + h) << 8) + o];

    float4 zsum = block_sum4(make_float4(z[0], z[1], z[2], z[3]), red4);
    float4 zsq  = block_sum4(make_float4(z[0]*z[0], z[1]*z[1], z[2]*z[2], z[3]*z[3]), red4);

    float zn[N_SM];
    {
        float mus[4] = {zsum.x, zsum.y, zsum.z, zsum.w};
        float sqs[4] = {zsq.x, zsq.y, zsq.z, zsq.w};
#pragma unroll
        for (int s = 0; s < N_SM; s++) {
            float mu = mus[s] * (1.f / N_OUT);
            float var = sqs[s] * (1.f / N_OUT) - mu * mu;
            float rstd = rsqrtf(var + EPS_GN);
            int idx = ((s * N_HEADS + h) << 8) + o;
            zn[s] = (z[s] - mu) * rstd * g2g[idx] + g2b[idx];
        }
    }

    float4 zmax = block_max4(make_float4(zn[0], zn[1], zn[2], zn[3]), red4);
    float e[N_SM];
    e[0] = expf(zn[0] - zmax.x);
    e[1] = expf(zn[1] - zmax.y);
    e[2] = expf(zn[2] - zmax.z);
    e[3] = expf(zn[3] - zmax.w);
    float4 denom = block_sum4(make_float4(e[0], e[1], e[2], e[3]), red4);

    float osm = e[0] / denom.x + e[1] / denom.y + e[2] / denom.z + e[3] / denom.w;

    float lp = g_lp[o];
    float part = woo[h * 512 + o] * lp + woo[h * 512 + N_OUT + o] * osm;
    float logit = block_sum(part, red);
    float on_off = 1.f / (1.f + expf(-logit));

    float v = on_off * osm;
    out[o * N_HEADS + h] = fmaxf(v, TINY);
    float sc = v * g_scalar[h * N_OUT + o];
    out[N_OUT * N_HEADS + o * N_HEADS + h] = (fabsf(sc) <= TINY) ? TINY : sc;
}

extern "C" void kernel_launch(void* const* d_in, const int* in_sizes, int n_in,
                              void* d_out, int out_size)
{
    const float* x    = (const float*)d_in[0];
    const float* last = (const float*)d_in[1];
    const float* qw   = (const float*)d_in[2];
    const float* w1   = (const float*)d_in[3];
    const float* g1g  = (const float*)d_in[4];
    const float* g1b  = (const float*)d_in[5];
    const float* w2   = (const float*)d_in[6];
    const float* g2g  = (const float*)d_in[7];
    const float* g2b  = (const float*)d_in[8];
    const float* ws   = (const float*)d_in[9];
    const float* woo  = (const float*)d_in[10];
    float* out = (float*)d_out;

    K1<<<256, 512>>>(x, qw, w1);
    K2<<<64, 512>>>(g1g, g1b);
    K3<<<1296, 512>>>(w2, ws, last);
    K4<<<N_HEADS, 256>>>(g2g, g2b, woo, out);
}